// round 12
// baseline (speedup 1.0000x reference)
#include <cuda_runtime.h>
#include <cuda_fp16.h>
#include <cstdint>

// Problem constants
#define B_  32
#define C_  512
#define CI_ 256
#define N_  1024   // H*W

// ---------------- static device scratch ----------------
__device__ __align__(128) __half d_x16[(size_t)B_ * C_ * N_];
__device__ __align__(128) __half d_Wstk[768 * C_];              // [g;theta;phi] stacked
__device__ __align__(128) float  d_bstk[768];
__device__ __align__(128) __half d_Wz16[C_ * CI_];
__device__ __align__(128) __half d_GTP[(size_t)B_ * 768 * N_];  // [b][768][N]
__device__ __align__(128) __half d_Yh[(size_t)B_ * N_ * CI_];   // y [b][N][Ci]
__device__ __align__(128) __half d_WYh[(size_t)B_ * C_ * N_];
__device__ float d_ssum[C_];
__device__ float d_ssq[C_];

// ---------------- helpers ----------------
static __device__ __forceinline__ uint32_t smem_u32(const void* p) {
    uint32_t a;
    asm("{ .reg .u64 t; cvta.to.shared.u64 t, %1; cvt.u32.u64 %0, t; }" : "=r"(a) : "l"(p));
    return a;
}

#define CP16(dst, src) \
    asm volatile("cp.async.cg.shared.global [%0], [%1], 16;" :: "r"(dst), "l"(src))
#define CP_COMMIT() asm volatile("cp.async.commit_group;" ::: "memory")
#define CP_WAIT0()  asm volatile("cp.async.wait_group 0;" ::: "memory")
#define CP_WAIT1()  asm volatile("cp.async.wait_group 1;" ::: "memory")
#define CP_WAIT2()  asm volatile("cp.async.wait_group 2;" ::: "memory")

#define LDSM4(r, addr) \
    asm volatile("ldmatrix.sync.aligned.m8n8.x4.shared.b16 {%0,%1,%2,%3}, [%4];" \
        : "=r"((r)[0]), "=r"((r)[1]), "=r"((r)[2]), "=r"((r)[3]) : "r"(addr))
#define LDSM4T(r, addr) \
    asm volatile("ldmatrix.sync.aligned.m8n8.x4.trans.shared.b16 {%0,%1,%2,%3}, [%4];" \
        : "=r"((r)[0]), "=r"((r)[1]), "=r"((r)[2]), "=r"((r)[3]) : "r"(addr))

static __device__ __forceinline__ void mma_f16(float* c, const uint32_t* a, const uint32_t* b) {
    asm volatile(
        "mma.sync.aligned.m16n8k16.row.col.f32.f16.f16.f32 "
        "{%0,%1,%2,%3},{%4,%5,%6,%7},{%8,%9},{%0,%1,%2,%3};"
        : "+f"(c[0]), "+f"(c[1]), "+f"(c[2]), "+f"(c[3])
        : "r"(a[0]), "r"(a[1]), "r"(a[2]), "r"(a[3]), "r"(b[0]), "r"(b[1]));
}

static __device__ __forceinline__ uint32_t h2pack(float a, float b) {
    __half2 h = __floats2half2_rn(a, b);
    return *(uint32_t*)&h;
}

// =====================================================================
//     GEMM: 128x128 block, 128 threads (2x2 warps, 64x64 warp tiles)
//     3-stage cp.async pipeline. A always [M][K] K-major.
// =====================================================================
// SMEM: A bufs @0,16K,32K; B bufs @48K,64K,80K  (96 KB)
#define SMEM_BYTES (96 * 1024)

template <bool TR>
static __device__ __forceinline__ void stage_tile128(const __half* __restrict__ src, int ld,
                                                     uint32_t dst, int k0, int t) {
#pragma unroll
    for (int i = 0; i < 8; ++i) {
        int idx = t + i * 128;
        if constexpr (!TR) {
            int r = idx >> 3, c = idx & 7;
            const __half* s = src + (size_t)r * ld + k0 + c * 8;
            CP16(dst + r * 128 + ((c ^ (r & 7)) << 4), s);
        } else {
            int k = idx >> 4, c = idx & 15;
            const __half* s = src + (size_t)(k0 + k) * ld + c * 8;
            CP16(dst + k * 256 + ((c ^ (k & 7)) << 4), s);
        }
    }
}

template <bool TB, bool BIAS, bool STATS>
__global__ __launch_bounds__(128, 2)
void mm_f16(const __half* __restrict__ A, const __half* __restrict__ Bm,
            const float* __restrict__ bias, __half* __restrict__ Out,
            int K, int ldA, int ldB,
            long strideA, long strideB, long strideO,
            float* gs, float* gs2) {
    extern __shared__ __align__(128) char smem[];
    const uint32_t sb = smem_u32(smem);
    const int t = threadIdx.x;
    const int l = t & 31;
    const int w = t >> 5;            // 0..3
    const int wm = (w >> 1) * 64;
    const int wn = (w & 1) * 64;
    const int m0 = blockIdx.y * 128;
    const int n0 = blockIdx.x * 128;
    const __half* Ab = A  + (size_t)blockIdx.z * strideA + (size_t)m0 * ldA;
    const __half* Bb = Bm + (size_t)blockIdx.z * strideB + (TB ? n0 : (size_t)n0 * ldB);

    float acc[4][8][4];
#pragma unroll
    for (int mt = 0; mt < 4; ++mt)
#pragma unroll
        for (int nt = 0; nt < 8; ++nt)
#pragma unroll
            for (int q = 0; q < 4; ++q) acc[mt][nt][q] = 0.f;

    const int S = K / 64;
    stage_tile128<false>(Ab, ldA, sb,                 0, t);
    stage_tile128<TB>   (Bb, ldB, sb + 49152,         0, t);
    CP_COMMIT();
    stage_tile128<false>(Ab, ldA, sb + 16384,        64, t);
    stage_tile128<TB>   (Bb, ldB, sb + 49152 + 16384, 64, t);
    CP_COMMIT();

    int rb = 0;
    for (int s = 0; s < S; ++s) {
        if (s == S - 1) { CP_WAIT0(); } else { CP_WAIT1(); }
        __syncthreads();
        if (s + 2 < S) {
            int sbuf = rb >= 1 ? rb - 1 : rb + 2;
            stage_tile128<false>(Ab, ldA, sb + sbuf * 16384,         (s + 2) * 64, t);
            stage_tile128<TB>   (Bb, ldB, sb + 49152 + sbuf * 16384, (s + 2) * 64, t);
            CP_COMMIT();
        }

        const uint32_t abase = sb + rb * 16384;
        const uint32_t bbase = sb + 49152 + rb * 16384;
#pragma unroll
        for (int ks = 0; ks < 4; ++ks) {
            uint32_t af[4][4], bf[4][4];
#pragma unroll
            for (int mt = 0; mt < 4; ++mt) {
                int row = wm + mt * 16 + (l & 7) + ((l >> 3) & 1) * 8;
                int ch  = ks * 2 + (l >> 4);
                LDSM4(af[mt], abase + row * 128 + ((ch ^ (row & 7)) << 4));
            }
#pragma unroll
            for (int np = 0; np < 4; ++np) {
                if constexpr (!TB) {
                    int row = wn + np * 16 + (l & 7) + (l >> 4) * 8;
                    int ch  = ks * 2 + ((l >> 3) & 1);
                    LDSM4(bf[np], bbase + row * 128 + ((ch ^ (row & 7)) << 4));
                } else {
                    int kr = ks * 16 + (l & 7) + ((l >> 3) & 1) * 8;
                    int ch = ((wn + np * 16) >> 3) + (l >> 4);
                    LDSM4T(bf[np], bbase + kr * 256 + ((ch ^ (kr & 7)) << 4));
                }
            }
#pragma unroll
            for (int mt = 0; mt < 4; ++mt)
#pragma unroll
                for (int nt = 0; nt < 8; ++nt)
                    mma_f16(acc[mt][nt], af[mt], &bf[nt >> 1][(nt & 1) * 2]);
        }
        rb = rb == 2 ? 0 : rb + 1;
    }

    if constexpr (STATS) {
        __syncthreads();
        ((float*)smem)[t] = 0.f;
        ((float*)smem)[t + 128] = 0.f;
        __syncthreads();
    }

#pragma unroll
    for (int mt = 0; mt < 4; ++mt) {
        const int row = m0 + wm + mt * 16 + (l >> 2);
        float bv0 = 0.f, bv1 = 0.f;
        if constexpr (BIAS) { bv0 = bias[row]; bv1 = bias[row + 8]; }
        __half* Ob = Out + (size_t)blockIdx.z * strideO;
        float s0 = 0.f, q0 = 0.f, s1 = 0.f, q1 = 0.f;
#pragma unroll
        for (int nt = 0; nt < 8; ++nt) {
            const int col = n0 + wn + nt * 8 + 2 * (l & 3);
            float v00 = acc[mt][nt][0] + bv0, v01 = acc[mt][nt][1] + bv0;
            float v10 = acc[mt][nt][2] + bv1, v11 = acc[mt][nt][3] + bv1;
            *(__half2*)(Ob + (size_t)row * N_ + col)       = __floats2half2_rn(v00, v01);
            *(__half2*)(Ob + (size_t)(row + 8) * N_ + col) = __floats2half2_rn(v10, v11);
            if constexpr (STATS) {
                s0 += v00 + v01; q0 += v00 * v00 + v01 * v01;
                s1 += v10 + v11; q1 += v10 * v10 + v11 * v11;
            }
        }
        if constexpr (STATS) {
            s0 += __shfl_xor_sync(~0u, s0, 1); s0 += __shfl_xor_sync(~0u, s0, 2);
            q0 += __shfl_xor_sync(~0u, q0, 1); q0 += __shfl_xor_sync(~0u, q0, 2);
            s1 += __shfl_xor_sync(~0u, s1, 1); s1 += __shfl_xor_sync(~0u, s1, 2);
            q1 += __shfl_xor_sync(~0u, q1, 1); q1 += __shfl_xor_sync(~0u, q1, 2);
            if ((l & 3) == 0) {
                const int lr = wm + mt * 16 + (l >> 2);
                float* ss = (float*)smem;
                atomicAdd(ss + lr, s0);       atomicAdd(ss + 128 + lr, q0);
                atomicAdd(ss + lr + 8, s1);   atomicAdd(ss + 128 + lr + 8, q1);
            }
        }
    }

    if constexpr (STATS) {
        __syncthreads();
        atomicAdd(gs  + m0 + t, ((float*)smem)[t]);
        atomicAdd(gs2 + m0 + t, ((float*)smem)[t + 128]);
    }
}

// =====================================================================
//          Flash-fused attention (reads from stacked GTP tensor)
// =====================================================================
#define FL_SMEM (192 * 1024)
#define GSTRIDE ((size_t)768 * N_)

template <int ROWS>
static __device__ __forceinline__ void stage256(const __half* __restrict__ src, uint32_t dst, int t) {
#pragma unroll
    for (int i = 0; i < ROWS / 16; ++i) {
        int idx = t + i * 256;
        int r = idx >> 4, c = idx & 15;
        CP16(dst + r * 256 + ((c ^ (r & 7)) << 4), src + (size_t)r * N_ + c * 8);
    }
}

__global__ __launch_bounds__(256, 1)
void flash_kernel(const __half* __restrict__ GTP, __half* __restrict__ Y) {
    extern __shared__ __align__(128) char smem[];
    const uint32_t sb = smem_u32(smem);
    const int t = threadIdx.x, l = t & 31, w = t >> 5;
    const int n0 = blockIdx.x * 128;
    const __half* Gb = GTP + (size_t)blockIdx.y * GSTRIDE;
    const __half* Tb = Gb + (size_t)256 * N_;
    const __half* Pb = Gb + (size_t)512 * N_;
    const uint32_t ph0 = sb + 65536, gbuf = sb + 131072;

    float oacc[32][4];
#pragma unroll
    for (int nt = 0; nt < 32; ++nt)
#pragma unroll
        for (int q = 0; q < 4; ++q) oacc[nt][q] = 0.f;
    float M0 = -1e30f, M1 = -1e30f, L0 = 0.f, L1 = 0.f;

    stage256<256>(Tb + n0, sb, t);
    stage256<128>(Pb + 0, ph0, t);
    CP_COMMIT();
    stage256<256>(Gb + 0, gbuf, t);
    CP_COMMIT();
    stage256<128>(Pb + (size_t)128 * N_ + 0, ph0 + 32768, t);
    CP_COMMIT();

    for (int it = 0; it < 8; ++it) {
        const int m0 = it * 128;
        float sacc[16][4];
#pragma unroll
        for (int nt = 0; nt < 16; ++nt)
#pragma unroll
            for (int q = 0; q < 4; ++q) sacc[nt][q] = 0.f;

#pragma unroll
        for (int h = 0; h < 2; ++h) {
            if (h == 0) { CP_WAIT2(); }
            else if (it == 0 || it == 7) { CP_WAIT1(); } else { CP_WAIT2(); }
            __syncthreads();
            const uint32_t phb = ph0 + h * 32768;
#pragma unroll
            for (int j = 0; j < 8; ++j) {
                uint32_t af[4];
                {
                    int kr = (h * 8 + j) * 16 + (l & 7) + (l >> 4) * 8;
                    int ch = 2 * w + ((l >> 3) & 1);
                    LDSM4T(af, sb + kr * 256 + ((ch ^ (kr & 7)) << 4));
                }
#pragma unroll
                for (int jj = 0; jj < 8; ++jj) {
                    uint32_t bf[4];
                    {
                        int kr = j * 16 + (l & 7) + ((l >> 3) & 1) * 8;
                        int ch = 2 * jj + (l >> 4);
                        LDSM4T(bf, phb + kr * 256 + ((ch ^ (kr & 7)) << 4));
                    }
                    mma_f16(sacc[2 * jj],     af, bf);
                    mma_f16(sacc[2 * jj + 1], af, bf + 2);
                }
            }
            __syncthreads();
            if (it < 7) {
                stage256<128>(Pb + (size_t)(h * 128) * N_ + m0 + 128, phb, t);
                CP_COMMIT();
            }
        }

        float tmax0 = -1e30f, tmax1 = -1e30f;
#pragma unroll
        for (int nt = 0; nt < 16; ++nt) {
            tmax0 = fmaxf(tmax0, fmaxf(sacc[nt][0], sacc[nt][1]));
            tmax1 = fmaxf(tmax1, fmaxf(sacc[nt][2], sacc[nt][3]));
        }
        tmax0 = fmaxf(tmax0, __shfl_xor_sync(~0u, tmax0, 1));
        tmax0 = fmaxf(tmax0, __shfl_xor_sync(~0u, tmax0, 2));
        tmax1 = fmaxf(tmax1, __shfl_xor_sync(~0u, tmax1, 1));
        tmax1 = fmaxf(tmax1, __shfl_xor_sync(~0u, tmax1, 2));
        float Mn0 = fmaxf(M0, tmax0), Mn1 = fmaxf(M1, tmax1);
        float sc0 = __expf(M0 - Mn0), sc1 = __expf(M1 - Mn1);
        float ts0 = 0.f, ts1 = 0.f;
        uint32_t afp[8][4];
#pragma unroll
        for (int j = 0; j < 8; ++j) {
            float p00 = __expf(sacc[2 * j][0] - Mn0);
            float p01 = __expf(sacc[2 * j][1] - Mn0);
            float p02 = __expf(sacc[2 * j][2] - Mn1);
            float p03 = __expf(sacc[2 * j][3] - Mn1);
            float p10 = __expf(sacc[2 * j + 1][0] - Mn0);
            float p11 = __expf(sacc[2 * j + 1][1] - Mn0);
            float p12 = __expf(sacc[2 * j + 1][2] - Mn1);
            float p13 = __expf(sacc[2 * j + 1][3] - Mn1);
            ts0 += p00 + p01 + p10 + p11;
            ts1 += p02 + p03 + p12 + p13;
            afp[j][0] = h2pack(p00, p01);
            afp[j][1] = h2pack(p02, p03);
            afp[j][2] = h2pack(p10, p11);
            afp[j][3] = h2pack(p12, p13);
        }
        ts0 += __shfl_xor_sync(~0u, ts0, 1); ts0 += __shfl_xor_sync(~0u, ts0, 2);
        ts1 += __shfl_xor_sync(~0u, ts1, 1); ts1 += __shfl_xor_sync(~0u, ts1, 2);
        L0 = L0 * sc0 + ts0; L1 = L1 * sc1 + ts1;
        M0 = Mn0; M1 = Mn1;
#pragma unroll
        for (int nt = 0; nt < 32; ++nt) {
            oacc[nt][0] *= sc0; oacc[nt][1] *= sc0;
            oacc[nt][2] *= sc1; oacc[nt][3] *= sc1;
        }

        if (it < 7) { CP_WAIT2(); } else { CP_WAIT0(); }
        __syncthreads();
#pragma unroll
        for (int ks = 0; ks < 8; ++ks) {
#pragma unroll
            for (int jj = 0; jj < 16; ++jj) {
                uint32_t bf[4];
                {
                    int row = 16 * jj + (l & 7) + (l >> 4) * 8;
                    int ch  = ks * 2 + ((l >> 3) & 1);
                    LDSM4(bf, gbuf + row * 256 + ((ch ^ (row & 7)) << 4));
                }
                mma_f16(oacc[2 * jj],     afp[ks], bf);
                mma_f16(oacc[2 * jj + 1], afp[ks], bf + 2);
            }
        }
        __syncthreads();
        if (it < 7) {
            stage256<256>(Gb + m0 + 128, gbuf, t);
            CP_COMMIT();
        }
    }

    const float i0 = 1.f / L0, i1 = 1.f / L1;
    __half* Yb = Y + (size_t)blockIdx.y * N_ * CI_;
    const int row0 = n0 + w * 16 + (l >> 2);
#pragma unroll
    for (int nt = 0; nt < 32; ++nt) {
        const int col = nt * 8 + (l & 3) * 2;
        *(__half2*)(Yb + (size_t)row0 * CI_ + col) =
            __floats2half2_rn(oacc[nt][0] * i0, oacc[nt][1] * i0);
        *(__half2*)(Yb + (size_t)(row0 + 8) * CI_ + col) =
            __floats2half2_rn(oacc[nt][2] * i1, oacc[nt][3] * i1);
    }
}

// ---------------- prep: zero stats + cvt x + pack weights/biases ----------------
#define XQ_ (B_ * C_ * N_ / 4)       // 4194304
#define WQ_ ((768 * C_) / 4)         // 98304
#define ZQ_ ((C_ * CI_) / 4)         // 32768

__global__ __launch_bounds__(256)
void prep_kernel(const float* __restrict__ x,
                 const float* __restrict__ Wg, const float* __restrict__ Wt,
                 const float* __restrict__ Wp, const float* __restrict__ Wz,
                 const float* __restrict__ bg, const float* __restrict__ bt,
                 const float* __restrict__ bp,
                 __half* __restrict__ x16,
                 __half* __restrict__ Wstk, __half* __restrict__ Wz16,
                 float* __restrict__ bstk) {
    int i = blockIdx.x * 256 + threadIdx.x;
    if (i < XQ_) {
        float4 v = ((const float4*)x)[i];
        __half2 h0 = __floats2half2_rn(v.x, v.y);
        __half2 h1 = __floats2half2_rn(v.z, v.w);
        uint2 u = { *(uint32_t*)&h0, *(uint32_t*)&h1 };
        ((uint2*)x16)[i] = u;
        return;
    }
    int j = i - XQ_;
    if (j < WQ_) {
        int row = (j * 4) >> 9;
        int col = (j * 4) & 511;
        const float* src = row < 256 ? Wg + row * C_
                         : row < 512 ? Wt + (row - 256) * C_
                                     : Wp + (row - 512) * C_;
        float4 v = *(const float4*)(src + col);
        __half2 h0 = __floats2half2_rn(v.x, v.y);
        __half2 h1 = __floats2half2_rn(v.z, v.w);
        uint2 u = { *(uint32_t*)&h0, *(uint32_t*)&h1 };
        ((uint2*)Wstk)[j] = u;
    } else if (j < WQ_ + ZQ_) {
        int k = j - WQ_;
        float4 v = ((const float4*)Wz)[k];
        __half2 h0 = __floats2half2_rn(v.x, v.y);
        __half2 h1 = __floats2half2_rn(v.z, v.w);
        uint2 u = { *(uint32_t*)&h0, *(uint32_t*)&h1 };
        ((uint2*)Wz16)[k] = u;
    } else if (j < WQ_ + ZQ_ + 192) {
        int e = (j - WQ_ - ZQ_) * 4;
#pragma unroll
        for (int q = 0; q < 4; ++q) {
            int r = e + q;
            bstk[r] = r < 256 ? bg[r] : r < 512 ? bt[r - 256] : bp[r - 512];
        }
    } else if (j < WQ_ + ZQ_ + 192 + 128) {
        int c = (j - WQ_ - ZQ_ - 192) * 4;
#pragma unroll
        for (int q = 0; q < 4; ++q) { d_ssum[c + q] = 0.f; d_ssq[c + q] = 0.f; }
    }
}

// ---------------- finalize: BN scale/shift inline + residual (x16) ----------------
__global__ __launch_bounds__(256)
void finalize_kernel(const __half* __restrict__ WY, const __half* __restrict__ x16,
                     const float* __restrict__ gamma, const float* __restrict__ beta,
                     float* __restrict__ out) {
    size_t i4 = (size_t)blockIdx.x * 256 + threadIdx.x;
    int c = (int)((i4 >> 8) & (C_ - 1));            // whole block shares one channel
    const float invN = 1.0f / (float)(B_ * N_);
    float mean = d_ssum[c] * invN;
    float var  = d_ssq[c] * invN - mean * mean;
    float inv  = rsqrtf(var + 1e-5f);
    float sc   = gamma[c] * inv;
    float sh   = beta[c] - mean * sc;

    uint2 uw = ((const uint2*)WY)[i4];
    uint2 ux = ((const uint2*)x16)[i4];
    float2 w0 = __half22float2(*(__half2*)&uw.x);
    float2 w1 = __half22float2(*(__half2*)&uw.y);
    float2 x0 = __half22float2(*(__half2*)&ux.x);
    float2 x1 = __half22float2(*(__half2*)&ux.y);
    float4 o;
    o.x = w0.x * sc + sh + x0.x;
    o.y = w0.y * sc + sh + x0.y;
    o.z = w1.x * sc + sh + x1.x;
    o.w = w1.y * sc + sh + x1.y;
    ((float4*)out)[i4] = o;
}

// ---------------- launch ----------------
extern "C" void kernel_launch(void* const* d_in, const int* in_sizes, int n_in,
                              void* d_out, int out_size) {
    const float* x     = (const float*)d_in[0];
    const float* Wg    = (const float*)d_in[1];
    const float* bg    = (const float*)d_in[2];
    const float* Wt    = (const float*)d_in[3];
    const float* bt    = (const float*)d_in[4];
    const float* Wp    = (const float*)d_in[5];
    const float* bp    = (const float*)d_in[6];
    const float* Wz    = (const float*)d_in[7];
    const float* bz    = (const float*)d_in[8];
    const float* gamma = (const float*)d_in[9];
    const float* beta  = (const float*)d_in[10];
    float* out = (float*)d_out;

    __half *x16, *Wstk, *Wz16, *GTP, *Yh, *WYh;
    float *bstk, *gs, *gs2;
    cudaGetSymbolAddress((void**)&x16,  d_x16);
    cudaGetSymbolAddress((void**)&Wstk, d_Wstk);
    cudaGetSymbolAddress((void**)&Wz16, d_Wz16);
    cudaGetSymbolAddress((void**)&GTP,  d_GTP);
    cudaGetSymbolAddress((void**)&Yh,   d_Yh);
    cudaGetSymbolAddress((void**)&WYh,  d_WYh);
    cudaGetSymbolAddress((void**)&bstk, d_bstk);
    cudaGetSymbolAddress((void**)&gs,   d_ssum);
    cudaGetSymbolAddress((void**)&gs2,  d_ssq);

    cudaFuncSetAttribute(mm_f16<true,  true, false>, cudaFuncAttributeMaxDynamicSharedMemorySize, SMEM_BYTES);
    cudaFuncSetAttribute(mm_f16<false, true, true >, cudaFuncAttributeMaxDynamicSharedMemorySize, SMEM_BYTES);
    cudaFuncSetAttribute(flash_kernel, cudaFuncAttributeMaxDynamicSharedMemorySize, FL_SMEM);

    const long sC  = (long)C_ * N_;
    const long sCi = (long)CI_ * N_;

    prep_kernel<<<(XQ_ + WQ_ + ZQ_ + 192 + 128 + 255) / 256, 256>>>(
        x, Wg, Wt, Wp, Wz, bg, bt, bp, x16, Wstk, Wz16, bstk);

    // stacked projections: GTP[b] (768 x N) = Wstk (768 x C) * x[b] (C x N)
    mm_f16<true, true, false><<<dim3(8, 6, 32), 128, SMEM_BYTES>>>(
        Wstk, x16, bstk, GTP, C_, C_, N_, 0, sC, (long)GSTRIDE, nullptr, nullptr);

    // fused attention: Y[b][n][ci]
    flash_kernel<<<dim3(8, 32), 256, FL_SMEM>>>(GTP, Yh);

    // z-conv + BN partial stats: WY[b] (C x N) = Wz (C x Ci) * Y[b] (N x Ci)
    mm_f16<false, true, true><<<dim3(8, 4, 32), 128, SMEM_BYTES>>>(
        Wz16, Yh, bz, WYh, CI_, CI_, CI_, 0, sCi, sC, gs, gs2);

    finalize_kernel<<<(B_ * C_ * N_) / 4 / 256, 256>>>(WYh, x16, gamma, beta, out);
}

// round 13
// speedup vs baseline: 1.0005x; 1.0005x over previous
#include <cuda_runtime.h>
#include <cuda_fp16.h>
#include <cstdint>

// Problem constants
#define B_  32
#define C_  512
#define CI_ 256
#define N_  1024   // H*W

// ---------------- static device scratch ----------------
__device__ __align__(128) __half d_x16[(size_t)B_ * C_ * N_];
__device__ __align__(128) __half d_Wstk[768 * C_];              // [g;theta;phi] stacked
__device__ __align__(128) float  d_bstk[768];
__device__ __align__(128) __half d_Wz16[C_ * CI_];
__device__ __align__(128) __half d_GTP[(size_t)B_ * 768 * N_];  // [b][768][N]
__device__ __align__(128) __half d_Yh[(size_t)B_ * N_ * CI_];   // y [b][N][Ci]
__device__ __align__(128) __half d_WYh[(size_t)B_ * C_ * N_];
__device__ float d_ssum[C_];
__device__ float d_ssq[C_];

// ---------------- helpers ----------------
static __device__ __forceinline__ uint32_t smem_u32(const void* p) {
    uint32_t a;
    asm("{ .reg .u64 t; cvta.to.shared.u64 t, %1; cvt.u32.u64 %0, t; }" : "=r"(a) : "l"(p));
    return a;
}

#define CP16(dst, src) \
    asm volatile("cp.async.cg.shared.global [%0], [%1], 16;" :: "r"(dst), "l"(src))
#define CP_COMMIT() asm volatile("cp.async.commit_group;" ::: "memory")
#define CP_WAIT0()  asm volatile("cp.async.wait_group 0;" ::: "memory")
#define CP_WAIT1()  asm volatile("cp.async.wait_group 1;" ::: "memory")
#define CP_WAIT2()  asm volatile("cp.async.wait_group 2;" ::: "memory")

#define LDSM4(r, addr) \
    asm volatile("ldmatrix.sync.aligned.m8n8.x4.shared.b16 {%0,%1,%2,%3}, [%4];" \
        : "=r"((r)[0]), "=r"((r)[1]), "=r"((r)[2]), "=r"((r)[3]) : "r"(addr))
#define LDSM4T(r, addr) \
    asm volatile("ldmatrix.sync.aligned.m8n8.x4.trans.shared.b16 {%0,%1,%2,%3}, [%4];" \
        : "=r"((r)[0]), "=r"((r)[1]), "=r"((r)[2]), "=r"((r)[3]) : "r"(addr))

static __device__ __forceinline__ void mma_f16(float* c, const uint32_t* a, const uint32_t* b) {
    asm volatile(
        "mma.sync.aligned.m16n8k16.row.col.f32.f16.f16.f32 "
        "{%0,%1,%2,%3},{%4,%5,%6,%7},{%8,%9},{%0,%1,%2,%3};"
        : "+f"(c[0]), "+f"(c[1]), "+f"(c[2]), "+f"(c[3])
        : "r"(a[0]), "r"(a[1]), "r"(a[2]), "r"(a[3]), "r"(b[0]), "r"(b[1]));
}

static __device__ __forceinline__ uint32_t h2pack(float a, float b) {
    __half2 h = __floats2half2_rn(a, b);
    return *(uint32_t*)&h;
}

// =====================================================================
//     GEMM: 128x128 block, 128 threads (2x2 warps, 64x64 warp tiles)
//     3-stage cp.async pipeline. A always [M][K] K-major.
// =====================================================================
// SMEM: A bufs @0,16K,32K; B bufs @48K,64K,80K  (96 KB)
#define SMEM_BYTES (96 * 1024)

template <bool TR>
static __device__ __forceinline__ void stage_tile128(const __half* __restrict__ src, int ld,
                                                     uint32_t dst, int k0, int t) {
#pragma unroll
    for (int i = 0; i < 8; ++i) {
        int idx = t + i * 128;
        if constexpr (!TR) {
            int r = idx >> 3, c = idx & 7;
            const __half* s = src + (size_t)r * ld + k0 + c * 8;
            CP16(dst + r * 128 + ((c ^ (r & 7)) << 4), s);
        } else {
            int k = idx >> 4, c = idx & 15;
            const __half* s = src + (size_t)(k0 + k) * ld + c * 8;
            CP16(dst + k * 256 + ((c ^ (k & 7)) << 4), s);
        }
    }
}

template <bool TB, bool BIAS, bool STATS>
__global__ __launch_bounds__(128, 2)
void mm_f16(const __half* __restrict__ A, const __half* __restrict__ Bm,
            const float* __restrict__ bias, __half* __restrict__ Out,
            int K, int ldA, int ldB,
            long strideA, long strideB, long strideO,
            float* gs, float* gs2) {
    extern __shared__ __align__(128) char smem[];
    const uint32_t sb = smem_u32(smem);
    const int t = threadIdx.x;
    const int l = t & 31;
    const int w = t >> 5;            // 0..3
    const int wm = (w >> 1) * 64;
    const int wn = (w & 1) * 64;
    const int m0 = blockIdx.y * 128;
    const int n0 = blockIdx.x * 128;
    const __half* Ab = A  + (size_t)blockIdx.z * strideA + (size_t)m0 * ldA;
    const __half* Bb = Bm + (size_t)blockIdx.z * strideB + (TB ? n0 : (size_t)n0 * ldB);

    float acc[4][8][4];
#pragma unroll
    for (int mt = 0; mt < 4; ++mt)
#pragma unroll
        for (int nt = 0; nt < 8; ++nt)
#pragma unroll
            for (int q = 0; q < 4; ++q) acc[mt][nt][q] = 0.f;

    const int S = K / 64;
    stage_tile128<false>(Ab, ldA, sb,                 0, t);
    stage_tile128<TB>   (Bb, ldB, sb + 49152,         0, t);
    CP_COMMIT();
    stage_tile128<false>(Ab, ldA, sb + 16384,        64, t);
    stage_tile128<TB>   (Bb, ldB, sb + 49152 + 16384, 64, t);
    CP_COMMIT();

    int rb = 0;
    for (int s = 0; s < S; ++s) {
        if (s == S - 1) { CP_WAIT0(); } else { CP_WAIT1(); }
        __syncthreads();
        if (s + 2 < S) {
            int sbuf = rb >= 1 ? rb - 1 : rb + 2;
            stage_tile128<false>(Ab, ldA, sb + sbuf * 16384,         (s + 2) * 64, t);
            stage_tile128<TB>   (Bb, ldB, sb + 49152 + sbuf * 16384, (s + 2) * 64, t);
            CP_COMMIT();
        }

        const uint32_t abase = sb + rb * 16384;
        const uint32_t bbase = sb + 49152 + rb * 16384;
#pragma unroll
        for (int ks = 0; ks < 4; ++ks) {
            uint32_t af[4][4], bf[4][4];
#pragma unroll
            for (int mt = 0; mt < 4; ++mt) {
                int row = wm + mt * 16 + (l & 7) + ((l >> 3) & 1) * 8;
                int ch  = ks * 2 + (l >> 4);
                LDSM4(af[mt], abase + row * 128 + ((ch ^ (row & 7)) << 4));
            }
#pragma unroll
            for (int np = 0; np < 4; ++np) {
                if constexpr (!TB) {
                    int row = wn + np * 16 + (l & 7) + (l >> 4) * 8;
                    int ch  = ks * 2 + ((l >> 3) & 1);
                    LDSM4(bf[np], bbase + row * 128 + ((ch ^ (row & 7)) << 4));
                } else {
                    int kr = ks * 16 + (l & 7) + ((l >> 3) & 1) * 8;
                    int ch = ((wn + np * 16) >> 3) + (l >> 4);
                    LDSM4T(bf[np], bbase + kr * 256 + ((ch ^ (kr & 7)) << 4));
                }
            }
#pragma unroll
            for (int mt = 0; mt < 4; ++mt)
#pragma unroll
                for (int nt = 0; nt < 8; ++nt)
                    mma_f16(acc[mt][nt], af[mt], &bf[nt >> 1][(nt & 1) * 2]);
        }
        rb = rb == 2 ? 0 : rb + 1;
    }

    if constexpr (STATS) {
        __syncthreads();
        ((float*)smem)[t] = 0.f;
        ((float*)smem)[t + 128] = 0.f;
        __syncthreads();
    }

#pragma unroll
    for (int mt = 0; mt < 4; ++mt) {
        const int row = m0 + wm + mt * 16 + (l >> 2);
        float bv0 = 0.f, bv1 = 0.f;
        if constexpr (BIAS) { bv0 = bias[row]; bv1 = bias[row + 8]; }
        __half* Ob = Out + (size_t)blockIdx.z * strideO;
        float s0 = 0.f, q0 = 0.f, s1 = 0.f, q1 = 0.f;
#pragma unroll
        for (int nt = 0; nt < 8; ++nt) {
            const int col = n0 + wn + nt * 8 + 2 * (l & 3);
            float v00 = acc[mt][nt][0] + bv0, v01 = acc[mt][nt][1] + bv0;
            float v10 = acc[mt][nt][2] + bv1, v11 = acc[mt][nt][3] + bv1;
            *(__half2*)(Ob + (size_t)row * N_ + col)       = __floats2half2_rn(v00, v01);
            *(__half2*)(Ob + (size_t)(row + 8) * N_ + col) = __floats2half2_rn(v10, v11);
            if constexpr (STATS) {
                s0 += v00 + v01; q0 += v00 * v00 + v01 * v01;
                s1 += v10 + v11; q1 += v10 * v10 + v11 * v11;
            }
        }
        if constexpr (STATS) {
            s0 += __shfl_xor_sync(~0u, s0, 1); s0 += __shfl_xor_sync(~0u, s0, 2);
            q0 += __shfl_xor_sync(~0u, q0, 1); q0 += __shfl_xor_sync(~0u, q0, 2);
            s1 += __shfl_xor_sync(~0u, s1, 1); s1 += __shfl_xor_sync(~0u, s1, 2);
            q1 += __shfl_xor_sync(~0u, q1, 1); q1 += __shfl_xor_sync(~0u, q1, 2);
            if ((l & 3) == 0) {
                const int lr = wm + mt * 16 + (l >> 2);
                float* ss = (float*)smem;
                atomicAdd(ss + lr, s0);       atomicAdd(ss + 128 + lr, q0);
                atomicAdd(ss + lr + 8, s1);   atomicAdd(ss + 128 + lr + 8, q1);
            }
        }
    }

    if constexpr (STATS) {
        __syncthreads();
        atomicAdd(gs  + m0 + t, ((float*)smem)[t]);
        atomicAdd(gs2 + m0 + t, ((float*)smem)[t + 128]);
    }
}

// =====================================================================
//          Flash-fused attention (reads from stacked GTP tensor)
// =====================================================================
#define FL_SMEM (192 * 1024)
#define GSTRIDE ((size_t)768 * N_)

template <int ROWS>
static __device__ __forceinline__ void stage256(const __half* __restrict__ src, uint32_t dst, int t) {
#pragma unroll
    for (int i = 0; i < ROWS / 16; ++i) {
        int idx = t + i * 256;
        int r = idx >> 4, c = idx & 15;
        CP16(dst + r * 256 + ((c ^ (r & 7)) << 4), src + (size_t)r * N_ + c * 8);
    }
}

__global__ __launch_bounds__(256, 1)
void flash_kernel(const __half* __restrict__ GTP, __half* __restrict__ Y) {
    extern __shared__ __align__(128) char smem[];
    const uint32_t sb = smem_u32(smem);
    const int t = threadIdx.x, l = t & 31, w = t >> 5;
    const int n0 = blockIdx.x * 128;
    const __half* Gb = GTP + (size_t)blockIdx.y * GSTRIDE;
    const __half* Tb = Gb + (size_t)256 * N_;
    const __half* Pb = Gb + (size_t)512 * N_;
    const uint32_t ph0 = sb + 65536, gbuf = sb + 131072;

    float oacc[32][4];
#pragma unroll
    for (int nt = 0; nt < 32; ++nt)
#pragma unroll
        for (int q = 0; q < 4; ++q) oacc[nt][q] = 0.f;
    float M0 = -1e30f, M1 = -1e30f, L0 = 0.f, L1 = 0.f;

    stage256<256>(Tb + n0, sb, t);
    stage256<128>(Pb + 0, ph0, t);
    CP_COMMIT();
    stage256<256>(Gb + 0, gbuf, t);
    CP_COMMIT();
    stage256<128>(Pb + (size_t)128 * N_ + 0, ph0 + 32768, t);
    CP_COMMIT();

    for (int it = 0; it < 8; ++it) {
        const int m0 = it * 128;
        float sacc[16][4];
#pragma unroll
        for (int nt = 0; nt < 16; ++nt)
#pragma unroll
            for (int q = 0; q < 4; ++q) sacc[nt][q] = 0.f;

#pragma unroll
        for (int h = 0; h < 2; ++h) {
            if (h == 0) { CP_WAIT2(); }
            else if (it == 0 || it == 7) { CP_WAIT1(); } else { CP_WAIT2(); }
            __syncthreads();
            const uint32_t phb = ph0 + h * 32768;
#pragma unroll
            for (int j = 0; j < 8; ++j) {
                uint32_t af[4];
                {
                    int kr = (h * 8 + j) * 16 + (l & 7) + (l >> 4) * 8;
                    int ch = 2 * w + ((l >> 3) & 1);
                    LDSM4T(af, sb + kr * 256 + ((ch ^ (kr & 7)) << 4));
                }
#pragma unroll
                for (int jj = 0; jj < 8; ++jj) {
                    uint32_t bf[4];
                    {
                        int kr = j * 16 + (l & 7) + ((l >> 3) & 1) * 8;
                        int ch = 2 * jj + (l >> 4);
                        LDSM4T(bf, phb + kr * 256 + ((ch ^ (kr & 7)) << 4));
                    }
                    mma_f16(sacc[2 * jj],     af, bf);
                    mma_f16(sacc[2 * jj + 1], af, bf + 2);
                }
            }
            __syncthreads();
            if (it < 7) {
                stage256<128>(Pb + (size_t)(h * 128) * N_ + m0 + 128, phb, t);
                CP_COMMIT();
            }
        }

        float tmax0 = -1e30f, tmax1 = -1e30f;
#pragma unroll
        for (int nt = 0; nt < 16; ++nt) {
            tmax0 = fmaxf(tmax0, fmaxf(sacc[nt][0], sacc[nt][1]));
            tmax1 = fmaxf(tmax1, fmaxf(sacc[nt][2], sacc[nt][3]));
        }
        tmax0 = fmaxf(tmax0, __shfl_xor_sync(~0u, tmax0, 1));
        tmax0 = fmaxf(tmax0, __shfl_xor_sync(~0u, tmax0, 2));
        tmax1 = fmaxf(tmax1, __shfl_xor_sync(~0u, tmax1, 1));
        tmax1 = fmaxf(tmax1, __shfl_xor_sync(~0u, tmax1, 2));
        float Mn0 = fmaxf(M0, tmax0), Mn1 = fmaxf(M1, tmax1);
        float sc0 = __expf(M0 - Mn0), sc1 = __expf(M1 - Mn1);
        float ts0 = 0.f, ts1 = 0.f;
        uint32_t afp[8][4];
#pragma unroll
        for (int j = 0; j < 8; ++j) {
            float p00 = __expf(sacc[2 * j][0] - Mn0);
            float p01 = __expf(sacc[2 * j][1] - Mn0);
            float p02 = __expf(sacc[2 * j][2] - Mn1);
            float p03 = __expf(sacc[2 * j][3] - Mn1);
            float p10 = __expf(sacc[2 * j + 1][0] - Mn0);
            float p11 = __expf(sacc[2 * j + 1][1] - Mn0);
            float p12 = __expf(sacc[2 * j + 1][2] - Mn1);
            float p13 = __expf(sacc[2 * j + 1][3] - Mn1);
            ts0 += p00 + p01 + p10 + p11;
            ts1 += p02 + p03 + p12 + p13;
            afp[j][0] = h2pack(p00, p01);
            afp[j][1] = h2pack(p02, p03);
            afp[j][2] = h2pack(p10, p11);
            afp[j][3] = h2pack(p12, p13);
        }
        ts0 += __shfl_xor_sync(~0u, ts0, 1); ts0 += __shfl_xor_sync(~0u, ts0, 2);
        ts1 += __shfl_xor_sync(~0u, ts1, 1); ts1 += __shfl_xor_sync(~0u, ts1, 2);
        L0 = L0 * sc0 + ts0; L1 = L1 * sc1 + ts1;
        M0 = Mn0; M1 = Mn1;
#pragma unroll
        for (int nt = 0; nt < 32; ++nt) {
            oacc[nt][0] *= sc0; oacc[nt][1] *= sc0;
            oacc[nt][2] *= sc1; oacc[nt][3] *= sc1;
        }

        if (it < 7) { CP_WAIT2(); } else { CP_WAIT0(); }
        __syncthreads();
#pragma unroll
        for (int ks = 0; ks < 8; ++ks) {
#pragma unroll
            for (int jj = 0; jj < 16; ++jj) {
                uint32_t bf[4];
                {
                    int row = 16 * jj + (l & 7) + (l >> 4) * 8;
                    int ch  = ks * 2 + ((l >> 3) & 1);
                    LDSM4(bf, gbuf + row * 256 + ((ch ^ (row & 7)) << 4));
                }
                mma_f16(oacc[2 * jj],     afp[ks], bf);
                mma_f16(oacc[2 * jj + 1], afp[ks], bf + 2);
            }
        }
        __syncthreads();
        if (it < 7) {
            stage256<256>(Gb + m0 + 128, gbuf, t);
            CP_COMMIT();
        }
    }

    const float i0 = 1.f / L0, i1 = 1.f / L1;
    __half* Yb = Y + (size_t)blockIdx.y * N_ * CI_;
    const int row0 = n0 + w * 16 + (l >> 2);
#pragma unroll
    for (int nt = 0; nt < 32; ++nt) {
        const int col = nt * 8 + (l & 3) * 2;
        *(__half2*)(Yb + (size_t)row0 * CI_ + col) =
            __floats2half2_rn(oacc[nt][0] * i0, oacc[nt][1] * i0);
        *(__half2*)(Yb + (size_t)(row0 + 8) * CI_ + col) =
            __floats2half2_rn(oacc[nt][2] * i1, oacc[nt][3] * i1);
    }
}

// ---------------- prep: zero stats + cvt x + pack weights/biases ----------------
#define XQ_ (B_ * C_ * N_ / 4)       // 4194304
#define WQ_ ((768 * C_) / 4)         // 98304
#define ZQ_ ((C_ * CI_) / 4)         // 32768

__global__ __launch_bounds__(256)
void prep_kernel(const float* __restrict__ x,
                 const float* __restrict__ Wg, const float* __restrict__ Wt,
                 const float* __restrict__ Wp, const float* __restrict__ Wz,
                 const float* __restrict__ bg, const float* __restrict__ bt,
                 const float* __restrict__ bp,
                 __half* __restrict__ x16,
                 __half* __restrict__ Wstk, __half* __restrict__ Wz16,
                 float* __restrict__ bstk) {
    int i = blockIdx.x * 256 + threadIdx.x;
    if (i < XQ_) {
        float4 v = ((const float4*)x)[i];
        __half2 h0 = __floats2half2_rn(v.x, v.y);
        __half2 h1 = __floats2half2_rn(v.z, v.w);
        uint2 u = { *(uint32_t*)&h0, *(uint32_t*)&h1 };
        ((uint2*)x16)[i] = u;
        return;
    }
    int j = i - XQ_;
    if (j < WQ_) {
        int row = (j * 4) >> 9;
        int col = (j * 4) & 511;
        const float* src = row < 256 ? Wg + row * C_
                         : row < 512 ? Wt + (row - 256) * C_
                                     : Wp + (row - 512) * C_;
        float4 v = *(const float4*)(src + col);
        __half2 h0 = __floats2half2_rn(v.x, v.y);
        __half2 h1 = __floats2half2_rn(v.z, v.w);
        uint2 u = { *(uint32_t*)&h0, *(uint32_t*)&h1 };
        ((uint2*)Wstk)[j] = u;
    } else if (j < WQ_ + ZQ_) {
        int k = j - WQ_;
        float4 v = ((const float4*)Wz)[k];
        __half2 h0 = __floats2half2_rn(v.x, v.y);
        __half2 h1 = __floats2half2_rn(v.z, v.w);
        uint2 u = { *(uint32_t*)&h0, *(uint32_t*)&h1 };
        ((uint2*)Wz16)[k] = u;
    } else if (j < WQ_ + ZQ_ + 192) {
        int e = (j - WQ_ - ZQ_) * 4;
#pragma unroll
        for (int q = 0; q < 4; ++q) {
            int r = e + q;
            bstk[r] = r < 256 ? bg[r] : r < 512 ? bt[r - 256] : bp[r - 512];
        }
    } else if (j < WQ_ + ZQ_ + 192 + 128) {
        int c = (j - WQ_ - ZQ_ - 192) * 4;
#pragma unroll
        for (int q = 0; q < 4; ++q) { d_ssum[c + q] = 0.f; d_ssq[c + q] = 0.f; }
    }
}

// ---------------- finalize: BN scale/shift inline + residual (x16) ----------------
__global__ __launch_bounds__(256)
void finalize_kernel(const __half* __restrict__ WY, const __half* __restrict__ x16,
                     const float* __restrict__ gamma, const float* __restrict__ beta,
                     float* __restrict__ out) {
    size_t i4 = (size_t)blockIdx.x * 256 + threadIdx.x;
    int c = (int)((i4 >> 8) & (C_ - 1));            // whole block shares one channel
    const float invN = 1.0f / (float)(B_ * N_);
    float mean = d_ssum[c] * invN;
    float var  = d_ssq[c] * invN - mean * mean;
    float inv  = rsqrtf(var + 1e-5f);
    float sc   = gamma[c] * inv;
    float sh   = beta[c] - mean * sc;

    uint2 uw = ((const uint2*)WY)[i4];
    uint2 ux = ((const uint2*)x16)[i4];
    float2 w0 = __half22float2(*(__half2*)&uw.x);
    float2 w1 = __half22float2(*(__half2*)&uw.y);
    float2 x0 = __half22float2(*(__half2*)&ux.x);
    float2 x1 = __half22float2(*(__half2*)&ux.y);
    float4 o;
    o.x = w0.x * sc + sh + x0.x;
    o.y = w0.y * sc + sh + x0.y;
    o.z = w1.x * sc + sh + x1.x;
    o.w = w1.y * sc + sh + x1.y;
    ((float4*)out)[i4] = o;
}

// ---------------- launch ----------------
extern "C" void kernel_launch(void* const* d_in, const int* in_sizes, int n_in,
                              void* d_out, int out_size) {
    const float* x     = (const float*)d_in[0];
    const float* Wg    = (const float*)d_in[1];
    const float* bg    = (const float*)d_in[2];
    const float* Wt    = (const float*)d_in[3];
    const float* bt    = (const float*)d_in[4];
    const float* Wp    = (const float*)d_in[5];
    const float* bp    = (const float*)d_in[6];
    const float* Wz    = (const float*)d_in[7];
    const float* bz    = (const float*)d_in[8];
    const float* gamma = (const float*)d_in[9];
    const float* beta  = (const float*)d_in[10];
    float* out = (float*)d_out;

    __half *x16, *Wstk, *Wz16, *GTP, *Yh, *WYh;
    float *bstk, *gs, *gs2;
    cudaGetSymbolAddress((void**)&x16,  d_x16);
    cudaGetSymbolAddress((void**)&Wstk, d_Wstk);
    cudaGetSymbolAddress((void**)&Wz16, d_Wz16);
    cudaGetSymbolAddress((void**)&GTP,  d_GTP);
    cudaGetSymbolAddress((void**)&Yh,   d_Yh);
    cudaGetSymbolAddress((void**)&WYh,  d_WYh);
    cudaGetSymbolAddress((void**)&bstk, d_bstk);
    cudaGetSymbolAddress((void**)&gs,   d_ssum);
    cudaGetSymbolAddress((void**)&gs2,  d_ssq);

    cudaFuncSetAttribute(mm_f16<true,  true, false>, cudaFuncAttributeMaxDynamicSharedMemorySize, SMEM_BYTES);
    cudaFuncSetAttribute(mm_f16<false, true, true >, cudaFuncAttributeMaxDynamicSharedMemorySize, SMEM_BYTES);
    cudaFuncSetAttribute(flash_kernel, cudaFuncAttributeMaxDynamicSharedMemorySize, FL_SMEM);

    const long sC  = (long)C_ * N_;
    const long sCi = (long)CI_ * N_;

    prep_kernel<<<(XQ_ + WQ_ + ZQ_ + 192 + 128 + 255) / 256, 256>>>(
        x, Wg, Wt, Wp, Wz, bg, bt, bp, x16, Wstk, Wz16, bstk);

    // stacked projections: GTP[b] (768 x N) = Wstk (768 x C) * x[b] (C x N)
    mm_f16<true, true, false><<<dim3(8, 6, 32), 128, SMEM_BYTES>>>(
        Wstk, x16, bstk, GTP, C_, C_, N_, 0, sC, (long)GSTRIDE, nullptr, nullptr);

    // fused attention: Y[b][n][ci]
    flash_kernel<<<dim3(8, 32), 256, FL_SMEM>>>(GTP, Yh);

    // z-conv + BN partial stats: WY[b] (C x N) = Wz (C x Ci) * Y[b] (N x Ci)
    mm_f16<false, true, true><<<dim3(8, 4, 32), 128, SMEM_BYTES>>>(
        Wz16, Yh, bz, WYh, CI_, CI_, CI_, 0, sCi, sC, gs, gs2);

    finalize_kernel<<<(B_ * C_ * N_) / 4 / 256, 256>>>(WYh, x16, gamma, beta, out);
}